// round 10
// baseline (speedup 1.0000x reference)
#include <cuda_runtime.h>
#include <cstdint>

#define Hd 768
#define HV4 192          // Hd / 4 (float4 per row)
#define BGRAPH 256
#define AOUT 3129
#define SSPLIT 6         // row-splits per segment in pooling

// ---- device scratch (no allocations allowed) ----
__device__ int   g_bounds[2][BGRAPH + 1];            // node / edge segment bounds
__device__ float g_partial[2][SSPLIT][BGRAPH][Hd];   // pooling partials (9.4 MB)
__device__ float g_langg[BGRAPH * 3 * Hd];           // [256, 2304]
__device__ float g_mid1[BGRAPH * Hd];
__device__ float g_mid2[BGRAPH * Hd];

__device__ __forceinline__ float4 f4add(float4 a, float4 b) {
    a.x += b.x; a.y += b.y; a.z += b.z; a.w += b.w; return a;
}

// ---- 0. bias pre-inits for atomic GEMM targets. grid=(16, BGRAPH), block=256 ----
// n in [0,768)      -> mid1 = b_mid
// n in [768,1536)   -> mid2 = b_mid2
// n in [1536,1536+A)-> pred = b_ans
__global__ void init_all_kernel(float* __restrict__ pred,
                                const float* __restrict__ b_mid,
                                const float* __restrict__ b_mid2,
                                const float* __restrict__ b_ans) {
    const int b = blockIdx.y;
    const int n = blockIdx.x * 256 + threadIdx.x;
    if (n < Hd)             g_mid1[b * Hd + n]            = b_mid[n];
    else if (n < 2 * Hd)    g_mid2[b * Hd + (n - Hd)]     = b_mid2[n - Hd];
    else {
        const int m = n - 2 * Hd;
        if (m < AOUT)       pred[b * AOUT + m]            = b_ans[m];
    }
}

// ---- 1. segment bounds, once. grid=2 (node, edge), block=257 ----
__global__ void bounds_kernel(const int* __restrict__ node_seg, int nn,
                              const int* __restrict__ edge_seg, int ne) {
    const int* seg = blockIdx.x ? edge_seg : node_seg;
    const int  n   = blockIdx.x ? ne : nn;
    const int  v   = threadIdx.x;                // 0..256
    int lo = 0, hi = n;
    while (lo < hi) { int m = (lo + hi) >> 1; if (seg[m] < v) lo = m + 1; else hi = m; }
    g_bounds[blockIdx.x][v] = lo;
}

// ---- 2. pooling partial sums. grid=(BGRAPH, SSPLIT, 2), block=192 ----
// Block (b, s, z): sums a contiguous 1/S row-chunk of segment b of tensor z,
// full row width via float4 (LDG.128, 4-row unroll => MLP_p1 = 4, calibrated).
__global__ __launch_bounds__(HV4)
void pool_partial_kernel(const float* __restrict__ node_feat,
                         const float* __restrict__ edge_feat) {
    const int b = blockIdx.x, s = blockIdx.y, z = blockIdx.z;
    const float4* feat = (const float4*)(z ? edge_feat : node_feat);
    const int start = g_bounds[z][b];
    const int end   = g_bounds[z][b + 1];
    const int len   = end - start;
    const int chunk = (len + SSPLIT - 1) / SSPLIT;
    const int r0 = start + s * chunk;
    const int r1 = min(r0 + chunk, end);
    const int c = threadIdx.x;                   // float4 column 0..191

    float4 a0 = {0,0,0,0}, a1 = {0,0,0,0}, a2 = {0,0,0,0}, a3 = {0,0,0,0};
    const float4* p = feat + c;
    int r = r0;
    for (; r + 4 <= r1; r += 4) {
        a0 = f4add(a0, p[(size_t)(r + 0) * HV4]);
        a1 = f4add(a1, p[(size_t)(r + 1) * HV4]);
        a2 = f4add(a2, p[(size_t)(r + 2) * HV4]);
        a3 = f4add(a3, p[(size_t)(r + 3) * HV4]);
    }
    for (; r < r1; ++r) a0 = f4add(a0, p[(size_t)r * HV4]);
    float4 t = f4add(f4add(a0, a1), f4add(a2, a3));
    ((float4*)&g_partial[z][s][b][0])[c] = t;
}

// ---- 3. reduce partials -> lang_g columns. grid=(BGRAPH, 2), block=192 ----
__global__ void pool_reduce_kernel() {
    const int b = blockIdx.x, z = blockIdx.y, c = threadIdx.x;
    float4 acc = {0,0,0,0};
    #pragma unroll
    for (int s = 0; s < SSPLIT; s++)
        acc = f4add(acc, ((const float4*)&g_partial[z][s][b][0])[c]);
    ((float4*)&g_langg[b * (3 * Hd) + z * Hd])[c] = acc;
}

// ---- shared GEMM block body (R4-proven shape) ----
// BM=BN=64, BK=16, 256 threads, 4x4 thread tile, float4 LDS.
template <bool RELU_A, bool ATOMIC>
__device__ __forceinline__ void gemm_block(const float* __restrict__ A, int lda,
                                           const float* __restrict__ W,
                                           const float* __restrict__ bias,
                                           float* __restrict__ C, int ldc,
                                           int N, int bx, int by, int k0, int Kc) {
    const int BM = 64, BN = 64, BK = 16;
    __shared__ float As[BK][BM + 4];   // row = 272 B (16B-aligned)
    __shared__ float Ws[BK][BN];

    const int tid = threadIdx.x;
    const int tx = tid & 15;
    const int ty = tid >> 4;
    const int bm = bx * BM;
    const int bn = by * BN;

    float acc[4][4] = {};

    for (int ks = k0; ks < k0 + Kc; ks += BK) {
        #pragma unroll
        for (int i = 0; i < 4; i++) {
            int e = tid + i * 256;
            int r = e >> 4, c = e & 15;
            float v = A[(bm + r) * lda + ks + c];
            if (RELU_A) v = fmaxf(v, 0.f);
            As[c][r] = v;
        }
        #pragma unroll
        for (int i = 0; i < 4; i++) {
            int e = tid + i * 256;
            int r = e >> 6, c = e & 63;
            int n = bn + c;
            Ws[r][c] = (n < N) ? W[(ks + r) * N + n] : 0.f;
        }
        __syncthreads();

        #pragma unroll
        for (int k = 0; k < BK; k++) {
            float4 a = *reinterpret_cast<const float4*>(&As[k][ty * 4]);
            float4 b = *reinterpret_cast<const float4*>(&Ws[k][tx * 4]);
            const float av[4] = {a.x, a.y, a.z, a.w};
            const float bv[4] = {b.x, b.y, b.z, b.w};
            #pragma unroll
            for (int i = 0; i < 4; i++)
                #pragma unroll
                for (int j = 0; j < 4; j++)
                    acc[i][j] += av[i] * bv[j];
        }
        __syncthreads();
    }

    #pragma unroll
    for (int i = 0; i < 4; i++) {
        int m = bm + ty * 4 + i;
        #pragma unroll
        for (int j = 0; j < 4; j++) {
            int n = bn + tx * 4 + j;
            if (n < N) {
                if (ATOMIC) atomicAdd(&C[m * ldc + n], acc[i][j]);
                else        C[m * ldc + n] = acc[i][j] + bias[n];
            }
        }
    }
}

// ---- lang GEMM: non-atomic, full-K, bias in epilogue. grid=(4, 12) ----
__global__ __launch_bounds__(256)
void lang_gemm_kernel(const float* __restrict__ question,
                      const float* __restrict__ W_lang,
                      const float* __restrict__ b_lang) {
    gemm_block<false, false>(question, Hd, W_lang, b_lang,
                             g_langg + 2 * Hd, 3 * Hd, Hd,
                             blockIdx.x, blockIdx.y, 0, Hd);
}

// ---- split-K atomic GEMM wrapper (into bias-preinit C) ----
// a_sel: 1 = langg, 2 = mid1, 3 = mid2. c_sel: 2 = mid1, 3 = mid2, 0 = ext.
template <bool RELU_A>
__global__ __launch_bounds__(256)
void gemm_kernel(int a_sel, int lda, const float* __restrict__ W,
                 int c_sel, float* __restrict__ C_ext, int ldc,
                 int N, int K) {
    const float* A = (a_sel == 1) ? g_langg : (a_sel == 2) ? g_mid1 : g_mid2;
    float* C = (c_sel == 2) ? g_mid1 : (c_sel == 3) ? g_mid2 : C_ext;
    const int Kc = K / gridDim.z;
    gemm_block<RELU_A, true>(A, lda, W, nullptr, C, ldc, N,
                             blockIdx.x, blockIdx.y, blockIdx.z * Kc, Kc);
}

extern "C" void kernel_launch(void* const* d_in, const int* in_sizes, int n_in,
                              void* d_out, int out_size) {
    const float* node_feat = (const float*)d_in[0];
    const float* edge_feat = (const float*)d_in[1];
    const float* question  = (const float*)d_in[2];
    const int*   node_seg  = (const int*)  d_in[3];
    const int*   edge_seg  = (const int*)  d_in[4];
    const float* W_lang    = (const float*)d_in[5];
    const float* b_lang    = (const float*)d_in[6];
    const float* W_mid     = (const float*)d_in[7];
    const float* b_mid     = (const float*)d_in[8];
    const float* W_mid2    = (const float*)d_in[9];
    const float* b_mid2    = (const float*)d_in[10];
    const float* W_ans     = (const float*)d_in[11];
    const float* b_ans     = (const float*)d_in[12];
    float* pred = (float*)d_out;

    const int Nn = in_sizes[3];
    const int Ne = in_sizes[4];

    // 0. bias pre-inits (mid1 / mid2 / pred), one launch
    init_all_kernel<<<dim3((2 * Hd + AOUT + 255) / 256, BGRAPH), 256>>>(
        pred, b_mid, b_mid2, b_ans);

    // 1. segment bounds (both tensors)
    bounds_kernel<<<2, BGRAPH + 1>>>(node_seg, Nn, edge_seg, Ne);

    // 2-3. pooling: partials then reduce -> lang_g[:, 0:1536]
    pool_partial_kernel<<<dim3(BGRAPH, SSPLIT, 2), HV4>>>(node_feat, edge_feat);
    pool_reduce_kernel<<<dim3(BGRAPH, 2), HV4>>>();

    // 4. lang = q @ W_lang + b_lang -> lang_g[:, 1536:2304]  (non-atomic, full-K)
    lang_gemm_kernel<<<dim3(4, 12), 256>>>(question, W_lang, b_lang);

    // 5. mid1 = lang_g @ W_mid + b_mid        (split-K=12, atomic)
    gemm_kernel<false><<<dim3(4, 12, 12), 256>>>(1, 3 * Hd, W_mid, 2, nullptr, Hd,
                                                 Hd, 3 * Hd);

    // 6. mid2 = relu(mid1) @ W_mid2 + b_mid2  (split-K=6, atomic)
    gemm_kernel<true><<<dim3(4, 12, 6), 256>>>(2, Hd, W_mid2, 3, nullptr, Hd,
                                               Hd, Hd);

    // 7. pred = relu(mid2) @ W_ans + b_ans    (split-K=4, atomic)
    gemm_kernel<true><<<dim3(4, (AOUT + 63) / 64, 4), 256>>>(3, Hd, W_ans, 0, pred, AOUT,
                                                             AOUT, Hd);
}

// round 11
// speedup vs baseline: 1.0921x; 1.0921x over previous
#include <cuda_runtime.h>
#include <cstdint>

#define Hd 768
#define HV4 192          // Hd / 4 (float4 per row)
#define BGRAPH 256
#define AOUT 3129
#define SSPLIT 6         // row-splits per segment in pooling

// ---- device scratch (no allocations allowed) ----
__device__ int   g_bounds[2][BGRAPH + 1];            // node / edge segment bounds
__device__ float g_partial[2][SSPLIT][BGRAPH][Hd];   // pooling partials (9.4 MB)
__device__ float g_langg[BGRAPH * 3 * Hd];           // [256, 2304]
__device__ float g_mid1[BGRAPH * Hd];
__device__ float g_mid2[BGRAPH * Hd];

// Scratch selector: 0 = external pointer, 1 = langg, 2 = mid1, 3 = mid2.
__device__ __forceinline__ float* sel_buf(int sel, float* ext) {
    switch (sel) { case 1: return g_langg; case 2: return g_mid1; case 3: return g_mid2;
                   default: return ext; }
}
__device__ __forceinline__ const float* sel_buf_c(int sel, const float* ext) {
    switch (sel) { case 1: return g_langg; case 2: return g_mid1; case 3: return g_mid2;
                   default: return ext; }
}

__device__ __forceinline__ float4 f4add(float4 a, float4 b) {
    a.x += b.x; a.y += b.y; a.z += b.z; a.w += b.w; return a;
}

// ---- 0. ALL bias pre-inits + segment bounds in one launch. grid=(22, BGRAPH) ----
// Init roles (per batch row b = blockIdx.y, n = blockIdx.x*256+tid):
//   n in [0,768)    -> lang_g[:, 1536+n] = b_lang[n]
//   n in [768,1536) -> mid1 = b_mid ; n in [1536,2304) -> mid2 = b_mid2
//   n in [2304,...) -> pred = b_ans
// Bounds role: blocks (x==0, y<2) additionally binary-search the 257 segment
// bounds for tensor y (thread v computes bound v; thread 0 also v=256).
__global__ void init_all_kernel(float* __restrict__ pred,
                                const float* __restrict__ b_lang,
                                const float* __restrict__ b_mid,
                                const float* __restrict__ b_mid2,
                                const float* __restrict__ b_ans,
                                const int* __restrict__ node_seg, int nn,
                                const int* __restrict__ edge_seg, int ne) {
    const int b = blockIdx.y;
    const int n = blockIdx.x * 256 + threadIdx.x;
    if (n < Hd)             g_langg[b * 3 * Hd + 2 * Hd + n] = b_lang[n];
    else if (n < 2 * Hd)    g_mid1[b * Hd + (n - Hd)]        = b_mid[n - Hd];
    else if (n < 3 * Hd)    g_mid2[b * Hd + (n - 2 * Hd)]    = b_mid2[n - 2 * Hd];
    else {
        const int m = n - 3 * Hd;
        if (m < AOUT)       pred[b * AOUT + m]               = b_ans[m];
    }

    // segment bounds (merged to save one launch)
    if (blockIdx.x == 0 && b < 2) {
        const int* seg = b ? edge_seg : node_seg;
        const int  cnt = b ? ne : nn;
        for (int v = threadIdx.x; v <= BGRAPH; v += 256) {
            int lo = 0, hi = cnt;
            while (lo < hi) { int m = (lo + hi) >> 1; if (seg[m] < v) lo = m + 1; else hi = m; }
            g_bounds[b][v] = lo;
        }
    }
}

// ---- 1. pooling partial sums. grid=(BGRAPH, SSPLIT, 2), block=192 ----
// Block (b, s, z): sums a contiguous 1/S row-chunk of segment b of tensor z,
// full row width via float4 (LDG.128, 4-row unroll => MLP_p1 = 4, calibrated).
__global__ __launch_bounds__(HV4)
void pool_partial_kernel(const float* __restrict__ node_feat,
                         const float* __restrict__ edge_feat) {
    const int b = blockIdx.x, s = blockIdx.y, z = blockIdx.z;
    const float4* feat = (const float4*)(z ? edge_feat : node_feat);
    const int start = g_bounds[z][b];
    const int end   = g_bounds[z][b + 1];
    const int len   = end - start;
    const int chunk = (len + SSPLIT - 1) / SSPLIT;
    const int r0 = start + s * chunk;
    const int r1 = min(r0 + chunk, end);
    const int c = threadIdx.x;                   // float4 column 0..191

    float4 a0 = {0,0,0,0}, a1 = {0,0,0,0}, a2 = {0,0,0,0}, a3 = {0,0,0,0};
    const float4* p = feat + c;
    int r = r0;
    for (; r + 4 <= r1; r += 4) {
        a0 = f4add(a0, p[(size_t)(r + 0) * HV4]);
        a1 = f4add(a1, p[(size_t)(r + 1) * HV4]);
        a2 = f4add(a2, p[(size_t)(r + 2) * HV4]);
        a3 = f4add(a3, p[(size_t)(r + 3) * HV4]);
    }
    for (; r < r1; ++r) a0 = f4add(a0, p[(size_t)r * HV4]);
    float4 t = f4add(f4add(a0, a1), f4add(a2, a3));
    ((float4*)&g_partial[z][s][b][0])[c] = t;
}

// ---- 2. reduce partials -> lang_g columns. grid=(BGRAPH, 2), block=192 ----
__global__ void pool_reduce_kernel() {
    const int b = blockIdx.x, z = blockIdx.y, c = threadIdx.x;
    float4 acc = {0,0,0,0};
    #pragma unroll
    for (int s = 0; s < SSPLIT; s++)
        acc = f4add(acc, ((const float4*)&g_partial[z][s][b][0])[c]);
    ((float4*)&g_langg[b * (3 * Hd) + z * Hd])[c] = acc;
}

// ---- tiled fp32 GEMM: C[M,N] (+)= op(A) @ W (+ bias)  [R4 proven version] ----
// BM=BN=64, BK=16, 256 threads, 4x4 tile, float4 LDS in inner loop.
// gridDim.z = k_splits; ATOMIC => atomicAdd into bias-preinit C.
template <bool RELU_A, bool ATOMIC>
__global__ __launch_bounds__(256)
void gemm_kernel(int a_sel, const float* __restrict__ A_ext, int lda,
                 const float* __restrict__ W,
                 const float* __restrict__ bias,
                 int c_sel, float* __restrict__ C_ext, int c_off, int ldc,
                 int M, int N, int K) {
    const float* A = sel_buf_c(a_sel, A_ext);
    float* C = sel_buf(c_sel, C_ext) + c_off;

    const int BM = 64, BN = 64, BK = 16;
    __shared__ float As[BK][BM + 4];   // row = 272 B (16B-aligned)
    __shared__ float Ws[BK][BN];

    const int tid = threadIdx.x;
    const int tx = tid & 15;
    const int ty = tid >> 4;
    const int bm = blockIdx.x * BM;
    const int bn = blockIdx.y * BN;
    const int Kc = K / gridDim.z;
    const int k0 = blockIdx.z * Kc;

    float acc[4][4] = {};

    for (int ks = k0; ks < k0 + Kc; ks += BK) {
        #pragma unroll
        for (int i = 0; i < 4; i++) {
            int e = tid + i * 256;
            int r = e >> 4, c = e & 15;
            float v = A[(bm + r) * lda + ks + c];
            if (RELU_A) v = fmaxf(v, 0.f);
            As[c][r] = v;
        }
        #pragma unroll
        for (int i = 0; i < 4; i++) {
            int e = tid + i * 256;
            int r = e >> 6, c = e & 63;
            int n = bn + c;
            Ws[r][c] = (n < N) ? W[(ks + r) * N + n] : 0.f;
        }
        __syncthreads();

        #pragma unroll
        for (int k = 0; k < BK; k++) {
            float4 a = *reinterpret_cast<const float4*>(&As[k][ty * 4]);
            float4 b = *reinterpret_cast<const float4*>(&Ws[k][tx * 4]);
            const float av[4] = {a.x, a.y, a.z, a.w};
            const float bv[4] = {b.x, b.y, b.z, b.w};
            #pragma unroll
            for (int i = 0; i < 4; i++)
                #pragma unroll
                for (int j = 0; j < 4; j++)
                    acc[i][j] += av[i] * bv[j];
        }
        __syncthreads();
    }

    #pragma unroll
    for (int i = 0; i < 4; i++) {
        int m = bm + ty * 4 + i;
        #pragma unroll
        for (int j = 0; j < 4; j++) {
            int n = bn + tx * 4 + j;
            if (n < N) {
                if (ATOMIC) atomicAdd(&C[m * ldc + n], acc[i][j]);
                else        C[m * ldc + n] = acc[i][j] + bias[n];
            }
        }
    }
}

extern "C" void kernel_launch(void* const* d_in, const int* in_sizes, int n_in,
                              void* d_out, int out_size) {
    const float* node_feat = (const float*)d_in[0];
    const float* edge_feat = (const float*)d_in[1];
    const float* question  = (const float*)d_in[2];
    const int*   node_seg  = (const int*)  d_in[3];
    const int*   edge_seg  = (const int*)  d_in[4];
    const float* W_lang    = (const float*)d_in[5];
    const float* b_lang    = (const float*)d_in[6];
    const float* W_mid     = (const float*)d_in[7];
    const float* b_mid     = (const float*)d_in[8];
    const float* W_mid2    = (const float*)d_in[9];
    const float* b_mid2    = (const float*)d_in[10];
    const float* W_ans     = (const float*)d_in[11];
    const float* b_ans     = (const float*)d_in[12];
    float* pred = (float*)d_out;

    const int Nn = in_sizes[3];
    const int Ne = in_sizes[4];

    // 0. all bias pre-inits + segment bounds, one launch
    init_all_kernel<<<dim3((3 * Hd + AOUT + 255) / 256, BGRAPH), 256>>>(
        pred, b_lang, b_mid, b_mid2, b_ans, node_seg, Nn, edge_seg, Ne);

    // 1-2. pooling: partials then reduce -> lang_g[:, 0:1536]
    pool_partial_kernel<<<dim3(BGRAPH, SSPLIT, 2), HV4>>>(node_feat, edge_feat);
    pool_reduce_kernel<<<dim3(BGRAPH, 2), HV4>>>();

    // 3. lang = q @ W_lang + b_lang -> lang_g[:, 1536:2304]   (split-K=6)
    gemm_kernel<false, true><<<dim3(4, 12, 6), 256>>>(
        0, question, Hd, W_lang, nullptr, 1, nullptr, 2 * Hd, 3 * Hd, BGRAPH, Hd, Hd);

    // 4. mid1 = lang_g @ W_mid + b_mid                        (split-K=6)
    gemm_kernel<false, true><<<dim3(4, 12, 6), 256>>>(
        1, nullptr, 3 * Hd, W_mid, nullptr, 2, nullptr, 0, Hd, BGRAPH, Hd, 3 * Hd);

    // 5. mid2 = relu(mid1) @ W_mid2 + b_mid2                  (split-K=6)
    gemm_kernel<true, true><<<dim3(4, 12, 6), 256>>>(
        2, nullptr, Hd, W_mid2, nullptr, 3, nullptr, 0, Hd, BGRAPH, Hd, Hd);

    // 6. pred = relu(mid2) @ W_ans + b_ans                    (split-K=2)
    gemm_kernel<true, true><<<dim3(4, (AOUT + 63) / 64, 2), 256>>>(
        3, nullptr, Hd, W_ans, nullptr, 0, pred, 0, AOUT, BGRAPH, AOUT, Hd);
}

// round 12
// speedup vs baseline: 1.2722x; 1.1649x over previous
#include <cuda_runtime.h>
#include <cstdint>

#define Hd 768
#define HV4 192          // Hd / 4 (float4 per row)
#define BGRAPH 256
#define AOUT 3129
#define SSPLIT 6         // row-splits per segment in pooling

// ---- device scratch (no allocations allowed) ----
__device__ int   g_bounds[2][BGRAPH + 1];            // node / edge segment bounds
__device__ float g_partial[2][SSPLIT][BGRAPH][Hd];   // pooling partials (9.4 MB)
__device__ float g_langg[BGRAPH * 3 * Hd];           // [256, 2304]
__device__ float g_mid1[BGRAPH * Hd];
__device__ float g_mid2[BGRAPH * Hd];

// Scratch selector: 0 = external pointer, 1 = langg, 2 = mid1, 3 = mid2.
__device__ __forceinline__ float* sel_buf(int sel, float* ext) {
    switch (sel) { case 1: return g_langg; case 2: return g_mid1; case 3: return g_mid2;
                   default: return ext; }
}
__device__ __forceinline__ const float* sel_buf_c(int sel, const float* ext) {
    switch (sel) { case 1: return g_langg; case 2: return g_mid1; case 3: return g_mid2;
                   default: return ext; }
}

__device__ __forceinline__ float4 f4add(float4 a, float4 b) {
    a.x += b.x; a.y += b.y; a.z += b.z; a.w += b.w; return a;
}

// 3xTF32 split: v = hi + lo (both tf32-representable); dropped lo*lo ~ 2^-24.
__device__ __forceinline__ void tf32_split(float v, float& hi, float& lo) {
    uint32_t u;
    asm("cvt.rna.tf32.f32 %0, %1;" : "=r"(u) : "f"(v));
    hi = __uint_as_float(u);
    float r = v - hi;
    uint32_t u2;
    asm("cvt.rna.tf32.f32 %0, %1;" : "=r"(u2) : "f"(r));
    lo = __uint_as_float(u2);
}

#define MMA_TF32(c, a, b0, b1)                                               \
    asm volatile("mma.sync.aligned.m16n8k8.row.col.f32.tf32.tf32.f32 "       \
                 "{%0,%1,%2,%3}, {%4,%5,%6,%7}, {%8,%9}, {%0,%1,%2,%3};"     \
                 : "+f"(c[0]), "+f"(c[1]), "+f"(c[2]), "+f"(c[3])            \
                 : "r"(a[0]), "r"(a[1]), "r"(a[2]), "r"(a[3]),               \
                   "r"(b0), "r"(b1))

// ---- 0. ALL bias pre-inits + segment bounds in one launch. grid=(22, BGRAPH) ----
__global__ void init_all_kernel(float* __restrict__ pred,
                                const float* __restrict__ b_lang,
                                const float* __restrict__ b_mid,
                                const float* __restrict__ b_mid2,
                                const float* __restrict__ b_ans,
                                const int* __restrict__ node_seg, int nn,
                                const int* __restrict__ edge_seg, int ne) {
    const int b = blockIdx.y;
    const int n = blockIdx.x * 256 + threadIdx.x;
    if (n < Hd)             g_langg[b * 3 * Hd + 2 * Hd + n] = b_lang[n];
    else if (n < 2 * Hd)    g_mid1[b * Hd + (n - Hd)]        = b_mid[n - Hd];
    else if (n < 3 * Hd)    g_mid2[b * Hd + (n - 2 * Hd)]    = b_mid2[n - 2 * Hd];
    else {
        const int m = n - 3 * Hd;
        if (m < AOUT)       pred[b * AOUT + m]               = b_ans[m];
    }
    // segment bounds (merged to save one launch)
    if (blockIdx.x == 0 && b < 2) {
        const int* seg = b ? edge_seg : node_seg;
        const int  cnt = b ? ne : nn;
        for (int v = threadIdx.x; v <= BGRAPH; v += 256) {
            int lo = 0, hi = cnt;
            while (lo < hi) { int m = (lo + hi) >> 1; if (seg[m] < v) lo = m + 1; else hi = m; }
            g_bounds[b][v] = lo;
        }
    }
}

// ---- 1. pooling partial sums. grid=(BGRAPH, SSPLIT, 2), block=192 ----
__global__ __launch_bounds__(HV4)
void pool_partial_kernel(const float* __restrict__ node_feat,
                         const float* __restrict__ edge_feat) {
    const int b = blockIdx.x, s = blockIdx.y, z = blockIdx.z;
    const float4* feat = (const float4*)(z ? edge_feat : node_feat);
    const int start = g_bounds[z][b];
    const int end   = g_bounds[z][b + 1];
    const int len   = end - start;
    const int chunk = (len + SSPLIT - 1) / SSPLIT;
    const int r0 = start + s * chunk;
    const int r1 = min(r0 + chunk, end);
    const int c = threadIdx.x;                   // float4 column 0..191

    float4 a0 = {0,0,0,0}, a1 = {0,0,0,0}, a2 = {0,0,0,0}, a3 = {0,0,0,0};
    const float4* p = feat + c;
    int r = r0;
    for (; r + 4 <= r1; r += 4) {
        a0 = f4add(a0, p[(size_t)(r + 0) * HV4]);
        a1 = f4add(a1, p[(size_t)(r + 1) * HV4]);
        a2 = f4add(a2, p[(size_t)(r + 2) * HV4]);
        a3 = f4add(a3, p[(size_t)(r + 3) * HV4]);
    }
    for (; r < r1; ++r) a0 = f4add(a0, p[(size_t)r * HV4]);
    float4 t = f4add(f4add(a0, a1), f4add(a2, a3));
    ((float4*)&g_partial[z][s][b][0])[c] = t;
}

// ---- 2. reduce partials -> lang_g columns. grid=(BGRAPH, 2), block=192 ----
__global__ void pool_reduce_kernel() {
    const int b = blockIdx.x, z = blockIdx.y, c = threadIdx.x;
    float4 acc = {0,0,0,0};
    #pragma unroll
    for (int s = 0; s < SSPLIT; s++)
        acc = f4add(acc, ((const float4*)&g_partial[z][s][b][0])[c]);
    ((float4*)&g_langg[b * (3 * Hd) + z * Hd])[c] = acc;
}

// ---- 3xTF32 tensor-core GEMM: C[M,N] += op(A) @ W  (bias pre-loaded in C) ----
// BM=BN=64, BK=16, 256 threads = 8 warps laid out 4(M) x 2(N); each warp owns a
// 16x32 tile = 4 n8-tiles of mma.m16n8k8. 3 MMAs per tile per k8 (hi*hi, hi*lo,
// lo*hi). gridDim.z = k_splits; atomicAdd into bias-preinitialized C.
template <bool RELU_A>
__global__ __launch_bounds__(256)
void gemm_kernel(int a_sel, const float* __restrict__ A_ext, int lda,
                 const float* __restrict__ W,
                 int c_sel, float* __restrict__ C_ext, int c_off, int ldc,
                 int N, int K) {
    const float* A = sel_buf_c(a_sel, A_ext);
    float* C = sel_buf(c_sel, C_ext) + c_off;

    const int BM = 64, BN = 64, BK = 16;
    __shared__ float As_hi[BK][BM + 4], As_lo[BK][BM + 4];
    __shared__ float Ws_hi[BK][BN + 4], Ws_lo[BK][BN + 4];

    const int tid  = threadIdx.x;
    const int warp = tid >> 5;
    const int lane = tid & 31;
    const int wm   = warp & 3;        // m16 slot
    const int wn   = warp >> 2;       // n32 slot
    const int grp  = lane >> 2;       // 0..7
    const int tig  = lane & 3;        // 0..3
    const int bm = blockIdx.x * BM;
    const int bn = blockIdx.y * BN;
    const int Kc = K / gridDim.z;
    const int k0 = blockIdx.z * Kc;

    float acc[4][4] = {};             // [n8-tile][mma C regs]

    for (int ks = k0; ks < k0 + Kc; ks += BK) {
        // load A tile (64x16), split hi/lo
        #pragma unroll
        for (int i = 0; i < 4; i++) {
            int e = tid + i * 256;
            int r = e >> 4, c = e & 15;
            float v = A[(bm + r) * lda + ks + c];
            if (RELU_A) v = fmaxf(v, 0.f);
            float hi, lo; tf32_split(v, hi, lo);
            As_hi[c][r] = hi; As_lo[c][r] = lo;
        }
        // load W tile (16x64), split hi/lo (guard N edge)
        #pragma unroll
        for (int i = 0; i < 4; i++) {
            int e = tid + i * 256;
            int r = e >> 6, c = e & 63;
            int n = bn + c;
            float v = (n < N) ? W[(ks + r) * N + n] : 0.f;
            float hi, lo; tf32_split(v, hi, lo);
            Ws_hi[r][c] = hi; Ws_lo[r][c] = lo;
        }
        __syncthreads();

        #pragma unroll
        for (int k8 = 0; k8 < BK; k8 += 8) {
            const int m0 = wm * 16 + grp, m1 = m0 + 8;
            const int kc0 = k8 + tig, kc1 = k8 + tig + 4;
            uint32_t ah[4] = { __float_as_uint(As_hi[kc0][m0]),
                               __float_as_uint(As_hi[kc0][m1]),
                               __float_as_uint(As_hi[kc1][m0]),
                               __float_as_uint(As_hi[kc1][m1]) };
            uint32_t al[4] = { __float_as_uint(As_lo[kc0][m0]),
                               __float_as_uint(As_lo[kc0][m1]),
                               __float_as_uint(As_lo[kc1][m0]),
                               __float_as_uint(As_lo[kc1][m1]) };
            #pragma unroll
            for (int t = 0; t < 4; t++) {
                const int bc = wn * 32 + t * 8 + grp;
                uint32_t bh0 = __float_as_uint(Ws_hi[kc0][bc]);
                uint32_t bh1 = __float_as_uint(Ws_hi[kc1][bc]);
                uint32_t bl0 = __float_as_uint(Ws_lo[kc0][bc]);
                uint32_t bl1 = __float_as_uint(Ws_lo[kc1][bc]);
                MMA_TF32(acc[t], ah, bh0, bh1);
                MMA_TF32(acc[t], ah, bl0, bl1);
                MMA_TF32(acc[t], al, bh0, bh1);
            }
        }
        __syncthreads();
    }

    // epilogue: mma C layout -> atomicAdd into bias-preinit C
    const int mrow0 = bm + wm * 16 + grp;
    const int mrow1 = mrow0 + 8;
    #pragma unroll
    for (int t = 0; t < 4; t++) {
        const int n0 = bn + wn * 32 + t * 8 + tig * 2;
        if (n0 < N) {
            atomicAdd(&C[mrow0 * ldc + n0], acc[t][0]);
            atomicAdd(&C[mrow1 * ldc + n0], acc[t][2]);
        }
        if (n0 + 1 < N) {
            atomicAdd(&C[mrow0 * ldc + n0 + 1], acc[t][1]);
            atomicAdd(&C[mrow1 * ldc + n0 + 1], acc[t][3]);
        }
    }
}

extern "C" void kernel_launch(void* const* d_in, const int* in_sizes, int n_in,
                              void* d_out, int out_size) {
    const float* node_feat = (const float*)d_in[0];
    const float* edge_feat = (const float*)d_in[1];
    const float* question  = (const float*)d_in[2];
    const int*   node_seg  = (const int*)  d_in[3];
    const int*   edge_seg  = (const int*)  d_in[4];
    const float* W_lang    = (const float*)d_in[5];
    const float* b_lang    = (const float*)d_in[6];
    const float* W_mid     = (const float*)d_in[7];
    const float* b_mid     = (const float*)d_in[8];
    const float* W_mid2    = (const float*)d_in[9];
    const float* b_mid2    = (const float*)d_in[10];
    const float* W_ans     = (const float*)d_in[11];
    const float* b_ans     = (const float*)d_in[12];
    float* pred = (float*)d_out;

    const int Nn = in_sizes[3];
    const int Ne = in_sizes[4];

    // 0. all bias pre-inits + segment bounds, one launch
    init_all_kernel<<<dim3((3 * Hd + AOUT + 255) / 256, BGRAPH), 256>>>(
        pred, b_lang, b_mid, b_mid2, b_ans, node_seg, Nn, edge_seg, Ne);

    // 1-2. pooling: partials then reduce -> lang_g[:, 0:1536]
    pool_partial_kernel<<<dim3(BGRAPH, SSPLIT, 2), HV4>>>(node_feat, edge_feat);
    pool_reduce_kernel<<<dim3(BGRAPH, 2), HV4>>>();

    // 3. lang = q @ W_lang + b_lang -> lang_g[:, 1536:2304]   (split-K=6)
    gemm_kernel<false><<<dim3(4, 12, 6), 256>>>(
        0, question, Hd, W_lang, 1, nullptr, 2 * Hd, 3 * Hd, Hd, Hd);

    // 4. mid1 = lang_g @ W_mid + b_mid                        (split-K=6)
    gemm_kernel<false><<<dim3(4, 12, 6), 256>>>(
        1, nullptr, 3 * Hd, W_mid, 2, nullptr, 0, Hd, Hd, 3 * Hd);

    // 5. mid2 = relu(mid1) @ W_mid2 + b_mid2                  (split-K=6)
    gemm_kernel<true><<<dim3(4, 12, 6), 256>>>(
        2, nullptr, Hd, W_mid2, 3, nullptr, 0, Hd, Hd, Hd);

    // 6. pred = relu(mid2) @ W_ans + b_ans                    (split-K=2)
    gemm_kernel<true><<<dim3(4, (AOUT + 63) / 64, 2), 256>>>(
        3, nullptr, Hd, W_ans, 0, pred, 0, AOUT, AOUT, Hd);
}